// round 11
// baseline (speedup 1.0000x reference)
#include <cuda_runtime.h>
#include <cuda_bf16.h>
#include <cuda_fp16.h>
#include <math.h>
#include <stdint.h>

#define SQ   2048
#define HID  2048
#define NH   16
#define HD   128
#define HALF 64
#define GS   128
#define NEG_INF (-3.402823e38f)

// ======================= PTX helpers (baseline sm_103 — NO tcgen05) =======================
__device__ __forceinline__ uint32_t smem_u32(const void* p) {
    uint32_t a;
    asm("{ .reg .u64 t; cvta.to.shared.u64 t, %1; cvt.u32.u64 %0, t; }" : "=r"(a) : "l"(p));
    return a;
}
#define SW128(o) ((o) ^ (((o) >> 3) & 0x70))
#define SW64(o)  ((o) ^ (((o) >> 3) & 0x30))

#define CPASYNC16(dst, src) \
    asm volatile("cp.async.cg.shared.global [%0], [%1], 16;" :: "r"(dst), "l"(src))
#define CPCOMMIT() asm volatile("cp.async.commit_group;" ::: "memory")
#define CPWAIT1()  asm volatile("cp.async.wait_group 1;" ::: "memory")

#define LDSM4(r, addr) \
    asm volatile("ldmatrix.sync.aligned.m8n8.x4.shared.b16 {%0,%1,%2,%3}, [%4];" \
                 : "=r"((r)[0]), "=r"((r)[1]), "=r"((r)[2]), "=r"((r)[3]) : "r"(addr))
#define LDSM2(r, addr) \
    asm volatile("ldmatrix.sync.aligned.m8n8.x2.shared.b16 {%0,%1}, [%2];" \
                 : "=r"((r)[0]), "=r"((r)[1]) : "r"(addr))

#define MMA_BF16(d, a, b) \
    asm volatile("mma.sync.aligned.m16n8k16.row.col.f32.bf16.bf16.f32 " \
                 "{%0,%1,%2,%3}, {%4,%5,%6,%7}, {%8,%9}, {%0,%1,%2,%3};" \
                 : "+f"((d)[0]), "+f"((d)[1]), "+f"((d)[2]), "+f"((d)[3]) \
                 : "r"((a)[0]), "r"((a)[1]), "r"((a)[2]), "r"((a)[3]), \
                   "r"((b)[0]), "r"((b)[1]))
#define MMA_F16(d, a, b) \
    asm volatile("mma.sync.aligned.m16n8k16.row.col.f32.f16.f16.f32 " \
                 "{%0,%1,%2,%3}, {%4,%5,%6,%7}, {%8,%9}, {%0,%1,%2,%3};" \
                 : "+f"((d)[0]), "+f"((d)[1]), "+f"((d)[2]), "+f"((d)[3]) \
                 : "r"((a)[0]), "r"((a)[1]), "r"((a)[2]), "r"((a)[3]), \
                   "r"((b)[0]), "r"((b)[1]))
#define MMA_S8(d, a, b) \
    asm volatile("mma.sync.aligned.m16n8k32.row.col.s32.s8.s8.s32 " \
                 "{%0,%1,%2,%3}, {%4,%5,%6,%7}, {%8,%9}, {%0,%1,%2,%3};" \
                 : "+r"((d)[0]), "+r"((d)[1]), "+r"((d)[2]), "+r"((d)[3]) \
                 : "r"((a)[0]), "r"((a)[1]), "r"((a)[2]), "r"((a)[3]), \
                   "r"((b)[0]), "r"((b)[1]))

// ======================= device scratch =======================
__device__ int8_t        g_wq8[4][(size_t)HID * HID];     // ternary q in int8 (exact)
__device__ float         g_wsc[4][(size_t)HID * 16];      // per-row per-K-group scales
__device__ int8_t        g_xhi[(size_t)SQ * HID], g_xlo[(size_t)SQ * HID];
__device__ float         g_sx[SQ];
__device__ int8_t        g_ahi[(size_t)SQ * HID], g_alo[(size_t)SQ * HID];
__device__ float         g_sa[SQ];
__device__ float         g_proj[3][(size_t)SQ * HID];
__device__ __nv_bfloat16 g_qh[NH][SQ * HD], g_ql[NH][SQ * HD];
__device__ __nv_bfloat16 g_kh[NH][SQ * HD], g_kl[NH][SQ * HD];
__device__ __half        g_vth[NH][HD * SQ], g_vtl[NH][HD * SQ];  // V^T [d][s] fp16 hi/lo
__device__ float         g_attn[(size_t)SQ * HID];
__device__ float         g_cos[SQ * HALF], g_sin[SQ * HALF];

__device__ __forceinline__ void bsplit(float x, __nv_bfloat16& h, __nv_bfloat16& l) {
    h = __float2bfloat16(x);
    l = __float2bfloat16(x - __bfloat162float(h));
}

// ======================= small kernels =======================
__global__ void rope_tables_kernel() {
    int s = blockIdx.x, i = threadIdx.x;
    float inv = (float)(1.0 / pow(10000.0, (double)i / 64.0));
    float ph = (float)s * inv;
    g_cos[s * HALF + i] = cosf(ph);
    g_sin[s * HALF + i] = sinf(ph);
}

// one warp per 128-elem group; exact ternary int8 q + fp32 group scale
__global__ void quantize_tern_kernel(const float* __restrict__ w,
                                     int8_t* __restrict__ q,
                                     float* __restrict__ sc) {
    int gid  = blockIdx.x * 8 + (threadIdx.x >> 5);
    int lane = threadIdx.x & 31;
    size_t base = (size_t)gid * GS + lane * 4;
    float4 v = *reinterpret_cast<const float4*>(w + base);
    float s = fabsf(v.x) + fabsf(v.y) + fabsf(v.z) + fabsf(v.w);
#pragma unroll
    for (int off = 16; off; off >>= 1) s += __shfl_xor_sync(0xffffffffu, s, off);
    float scale = fmaxf(s * 0.0078125f, 1e-8f);
    float vv[4] = {v.x, v.y, v.z, v.w};
    uint32_t pk = 0;
#pragma unroll
    for (int j = 0; j < 4; j++) {
        float wn = vv[j] / scale;
        int qv = (wn > 0.5f) ? 1 : ((wn < -0.5f) ? -1 : 0);
        pk |= ((uint32_t)(qv & 0xff)) << (j * 8);
    }
    *reinterpret_cast<uint32_t*>(q + base) = pk;
    if (lane == 0) sc[gid] = scale;
}

// per-row 15-bit int8 hi/lo quantization of fp32 activations
__global__ void quant8_kernel(const float* __restrict__ x,
                              int8_t* __restrict__ hi, int8_t* __restrict__ lo,
                              float* __restrict__ sxArr) {
    int row = blockIdx.x, tid = threadIdx.x;
    const float* xr = x + (size_t)row * HID;
    __shared__ float red[8];
    float4 v0 = *reinterpret_cast<const float4*>(xr + tid * 8);
    float4 v1 = *reinterpret_cast<const float4*>(xr + tid * 8 + 4);
    float f[8] = {v0.x, v0.y, v0.z, v0.w, v1.x, v1.y, v1.z, v1.w};
    float mx = 0.f;
#pragma unroll
    for (int j = 0; j < 8; j++) mx = fmaxf(mx, fabsf(f[j]));
#pragma unroll
    for (int off = 16; off; off >>= 1) mx = fmaxf(mx, __shfl_xor_sync(0xffffffffu, mx, off));
    if ((tid & 31) == 0) red[tid >> 5] = mx;
    __syncthreads();
    mx = fmaxf(red[0], red[1]);
#pragma unroll
    for (int j = 2; j < 8; j++) mx = fmaxf(mx, red[j]);
    mx = fmaxf(mx, 1e-20f);
    if (tid == 0) sxArr[row] = mx * (1.f / 16128.f);
    float inv = 16128.f / mx;
    uint32_t ph[2], pl[2];
#pragma unroll
    for (int w = 0; w < 2; w++) {
        uint32_t uh = 0, ul = 0;
#pragma unroll
        for (int j = 0; j < 4; j++) {
            int iv = __float2int_rn(f[w * 4 + j] * inv);
            int h = (iv + 64) >> 7;         // round(iv/128)
            int l = iv - (h << 7);          // in [-64, 63]
            uh |= ((uint32_t)(h & 0xff)) << (j * 8);
            ul |= ((uint32_t)(l & 0xff)) << (j * 8);
        }
        ph[w] = uh; pl[w] = ul;
    }
    *reinterpret_cast<uint2*>(hi + (size_t)row * HID + tid * 8) = make_uint2(ph[0], ph[1]);
    *reinterpret_cast<uint2*>(lo + (size_t)row * HID + tid * 8) = make_uint2(pl[0], pl[1]);
}

__global__ void rope_reshape_kernel(int which) {
    int s = blockIdx.x, h = blockIdx.y, d = threadIdx.x;  // d in [0,64)
    const float* src = g_proj[which] + (size_t)s * HID + h * HD;
    float x1 = src[d], x2 = src[d + HALF];
    float c = g_cos[s * HALF + d], sn = g_sin[s * HALF + d];
    float o1 = x1 * c - x2 * sn;
    float o2 = x1 * sn + x2 * c;
    __nv_bfloat16 h1, l1, h2, l2;
    bsplit(o1, h1, l1); bsplit(o2, h2, l2);
    __nv_bfloat16* dh = (which == 0 ? g_qh[h] : g_kh[h]) + (size_t)s * HD;
    __nv_bfloat16* dl = (which == 0 ? g_ql[h] : g_kl[h]) + (size_t)s * HD;
    dh[d] = h1; dh[d + HALF] = h2;
    dl[d] = l1; dl[d + HALF] = l2;
}

__global__ void vt_split_kernel() {
    __shared__ float t[32][33];
    int h = blockIdx.z, s0 = blockIdx.x * 32, d0 = blockIdx.y * 32;
    const float* src = g_proj[2] + (size_t)h * HD;
    for (int i = threadIdx.y; i < 32; i += 8)
        t[i][threadIdx.x] = src[(size_t)(s0 + i) * HID + d0 + threadIdx.x];
    __syncthreads();
    for (int i = threadIdx.y; i < 32; i += 8) {
        float v = t[threadIdx.x][i];
        __half hh = __float2half(v);
        __half ll = __float2half(v - __half2float(hh));
        size_t off = (size_t)(d0 + i) * SQ + s0 + threadIdx.x;
        g_vth[h][off] = hh; g_vtl[h][off] = ll;
    }
}

// ======================= flash attention (unchanged from R9) =======================
#define FL_SMEM 231424
#define FL_SCALE 0.08838834764831845f

__global__ void __launch_bounds__(256, 1)
flash_kernel(const int* __restrict__ mask, float* __restrict__ attn) {
    int h  = blockIdx.x;
    int qb = 15 - (int)blockIdx.y;
    extern __shared__ char smem[];
    uint32_t sb = smem_u32(smem);
    const uint32_t Qb = sb, Ab = sb + 65536u, Bb = sb + 131072u, Pb = sb + 196608u;
    float* red = reinterpret_cast<float*>(smem + 229376);
    int tid = threadIdx.x, lane = tid & 31, wid = tid >> 5;
    int wm = wid >> 2, wn = wid & 3, la = lane & 15;

    const __nv_bfloat16* qhp = g_qh[h]; const __nv_bfloat16* qlp = g_ql[h];
    const __nv_bfloat16* khp = g_kh[h]; const __nv_bfloat16* klp = g_kl[h];
    const __half* vhp = g_vth[h]; const __half* vlp = g_vtl[h];

#pragma unroll
    for (int j = 0; j < 16; j++) {
        int c = tid + j * 256; int b = c >> 10, id = c & 1023, row = id >> 3, ch = id & 7;
        const __nv_bfloat16* src = (ch < 4 ? qhp : qlp)
            + (size_t)(qb * 128 + row) * HD + b * 32 + (ch & 3) * 8;
        CPASYNC16(Qb + b * 16384u + SW128((uint32_t)(row * 128 + ch * 16)), src);
    }
    CPCOMMIT();

    auto load_k = [&](int kb) {
#pragma unroll
        for (int j = 0; j < 16; j++) {
            int c = tid + j * 256; int b = c >> 10, id = c & 1023, row = id >> 3, ch = id & 7;
            const __nv_bfloat16* src = (ch < 4 ? khp : klp)
                + (size_t)(kb * 128 + row) * HD + b * 32 + (ch & 3) * 8;
            CPASYNC16(Ab + b * 16384u + SW128((uint32_t)(row * 128 + ch * 16)), src);
        }
    };
    auto load_v = [&](int kb) {
#pragma unroll
        for (int j = 0; j < 16; j++) {
            int c = tid + j * 256; int b = c >> 10, id = c & 1023, row = id >> 3, ch = id & 7;
            const __half* src = (ch < 4 ? vhp : vlp)
                + (size_t)row * SQ + kb * 128 + b * 32 + (ch & 3) * 8;
            CPASYNC16(Bb + b * 16384u + SW128((uint32_t)(row * 128 + ch * 16)), src);
        }
    };
    load_k(0); CPCOMMIT();
    load_v(0); CPCOMMIT();

    float o[4][4][4];
    float mrow[4][2], lrow[4][2];
#pragma unroll
    for (int i = 0; i < 4; i++) {
#pragma unroll
        for (int j = 0; j < 4; j++)
#pragma unroll
            for (int r = 0; r < 4; r++) o[i][j][r] = 0.f;
        mrow[i][0] = NEG_INF; mrow[i][1] = NEG_INF;
        lrow[i][0] = 0.f;     lrow[i][1] = 0.f;
    }

    for (int s = 0; s <= qb; s++) {
        CPWAIT1();
        __syncthreads();

        float sacc[4][4][4];
#pragma unroll
        for (int i = 0; i < 4; i++)
#pragma unroll
            for (int j = 0; j < 4; j++)
#pragma unroll
                for (int r = 0; r < 4; r++) sacc[i][j][r] = 0.f;
#pragma unroll
        for (int kk = 0; kk < 8; kk++) {
            int b = kk >> 1, klo = kk & 1;
            uint32_t qh4[4][4], ql4[4][4], kh2[4][2], kl2[4][2];
#pragma unroll
            for (int i = 0; i < 4; i++) {
                uint32_t row = (uint32_t)(wm * 64 + i * 16 + la);
                uint32_t colh = (uint32_t)(klo * 32 + (lane >> 4) * 16);
                LDSM4(qh4[i], Qb + b * 16384u + SW128(row * 128 + colh));
                LDSM4(ql4[i], Qb + b * 16384u + SW128(row * 128 + 64 + colh));
            }
#pragma unroll
            for (int j = 0; j < 4; j++) {
                uint32_t krow = (uint32_t)(wn * 32 + j * 8 + (la & 7));
                uint32_t kc = (uint32_t)(klo * 32 + (la >> 3) * 16);
                LDSM2(kh2[j], Ab + b * 16384u + SW128(krow * 128 + kc));
                LDSM2(kl2[j], Ab + b * 16384u + SW128(krow * 128 + 64 + kc));
            }
#pragma unroll
            for (int i = 0; i < 4; i++)
#pragma unroll
                for (int j = 0; j < 4; j++) {
                    MMA_BF16(sacc[i][j], qh4[i], kh2[j]);
                    MMA_BF16(sacc[i][j], qh4[i], kl2[j]);
                    MMA_BF16(sacc[i][j], ql4[i], kh2[j]);
                }
        }

        bool diag = (s == qb);
#pragma unroll
        for (int j = 0; j < 4; j++) {
            int c0 = wn * 32 + j * 8 + (lane & 3) * 2;
            int cg = s * 128 + c0;
            bool mk0 = (__ldg(mask + cg) != 0), mk1 = (__ldg(mask + cg + 1) != 0);
#pragma unroll
            for (int i = 0; i < 4; i++) {
                int rg0 = qb * 128 + wm * 64 + i * 16 + (lane >> 2);
                int rg1 = rg0 + 8;
                float v0 = sacc[i][j][0] * FL_SCALE;
                float v1 = sacc[i][j][1] * FL_SCALE;
                float v2 = sacc[i][j][2] * FL_SCALE;
                float v3 = sacc[i][j][3] * FL_SCALE;
                if (!mk0 || (diag && cg     > rg0)) v0 = NEG_INF;
                if (!mk1 || (diag && cg + 1 > rg0)) v1 = NEG_INF;
                if (!mk0 || (diag && cg     > rg1)) v2 = NEG_INF;
                if (!mk1 || (diag && cg + 1 > rg1)) v3 = NEG_INF;
                sacc[i][j][0] = v0; sacc[i][j][1] = v1;
                sacc[i][j][2] = v2; sacc[i][j][3] = v3;
            }
        }

#pragma unroll
        for (int i = 0; i < 4; i++) {
            float a0 = NEG_INF, a1 = NEG_INF;
#pragma unroll
            for (int j = 0; j < 4; j++) {
                a0 = fmaxf(a0, fmaxf(sacc[i][j][0], sacc[i][j][1]));
                a1 = fmaxf(a1, fmaxf(sacc[i][j][2], sacc[i][j][3]));
            }
            a0 = fmaxf(a0, __shfl_xor_sync(0xffffffffu, a0, 1));
            a0 = fmaxf(a0, __shfl_xor_sync(0xffffffffu, a0, 2));
            a1 = fmaxf(a1, __shfl_xor_sync(0xffffffffu, a1, 1));
            a1 = fmaxf(a1, __shfl_xor_sync(0xffffffffu, a1, 2));
            if ((lane & 3) == 0) {
                int r0 = wm * 64 + i * 16 + (lane >> 2);
                red[r0 * 4 + wn] = a0;
                red[(r0 + 8) * 4 + wn] = a1;
            }
        }
        __syncthreads();

        float fsc[4][2], mnew[4][2];
#pragma unroll
        for (int i = 0; i < 4; i++)
#pragma unroll
            for (int rs = 0; rs < 2; rs++) {
                int r0 = wm * 64 + i * 16 + (lane >> 2) + rs * 8;
                float4 rv = *reinterpret_cast<float4*>(red + r0 * 4);
                float rm = fmaxf(fmaxf(rv.x, rv.y), fmaxf(rv.z, rv.w));
                float mn = fmaxf(mrow[i][rs], rm);
                fsc[i][rs] = __expf(mrow[i][rs] - mn);
                mnew[i][rs] = mn;
                mrow[i][rs] = mn;
            }

        float ps[4][2];
#pragma unroll
        for (int i = 0; i < 4; i++) { ps[i][0] = 0.f; ps[i][1] = 0.f; }
#pragma unroll
        for (int i = 0; i < 4; i++)
#pragma unroll
            for (int j = 0; j < 4; j++) {
                float p0 = __expf(sacc[i][j][0] - mnew[i][0]);
                float p1 = __expf(sacc[i][j][1] - mnew[i][0]);
                float p2 = __expf(sacc[i][j][2] - mnew[i][1]);
                float p3 = __expf(sacc[i][j][3] - mnew[i][1]);
                sacc[i][j][0] = p0; sacc[i][j][1] = p1;
                sacc[i][j][2] = p2; sacc[i][j][3] = p3;
                ps[i][0] += p0 + p1; ps[i][1] += p2 + p3;
            }
        __syncthreads();
#pragma unroll
        for (int i = 0; i < 4; i++) {
            float a0 = ps[i][0], a1 = ps[i][1];
            a0 += __shfl_xor_sync(0xffffffffu, a0, 1);
            a0 += __shfl_xor_sync(0xffffffffu, a0, 2);
            a1 += __shfl_xor_sync(0xffffffffu, a1, 1);
            a1 += __shfl_xor_sync(0xffffffffu, a1, 2);
            if ((lane & 3) == 0) {
                int r0 = wm * 64 + i * 16 + (lane >> 2);
                red[r0 * 4 + wn] = a0;
                red[(r0 + 8) * 4 + wn] = a1;
            }
        }
        __syncthreads();
#pragma unroll
        for (int i = 0; i < 4; i++)
#pragma unroll
            for (int rs = 0; rs < 2; rs++) {
                int r0 = wm * 64 + i * 16 + (lane >> 2) + rs * 8;
                float4 rv = *reinterpret_cast<float4*>(red + r0 * 4);
                float rsum = rv.x + rv.y + rv.z + rv.w;
                lrow[i][rs] = lrow[i][rs] * fsc[i][rs] + rsum;
            }
#pragma unroll
        for (int i = 0; i < 4; i++)
#pragma unroll
            for (int j = 0; j < 4; j++) {
                o[i][j][0] *= fsc[i][0]; o[i][j][1] *= fsc[i][0];
                o[i][j][2] *= fsc[i][1]; o[i][j][3] *= fsc[i][1];
            }

        if (s < qb) { load_k(s + 1); CPCOMMIT(); }

#pragma unroll
        for (int i = 0; i < 4; i++)
#pragma unroll
            for (int j = 0; j < 4; j++) {
                int c0 = wn * 32 + j * 8 + (lane & 3) * 2;
                int b = c0 >> 5, cc = c0 & 31;
                int r0 = wm * 64 + i * 16 + (lane >> 2);
                __half2 h0 = __floats2half2_rn(sacc[i][j][0], sacc[i][j][1]);
                __half2 h1 = __floats2half2_rn(sacc[i][j][2], sacc[i][j][3]);
                uint32_t a0 = Pb + b * 8192u + SW64((uint32_t)(r0 * 64 + cc * 2));
                uint32_t a1 = Pb + b * 8192u + SW64((uint32_t)((r0 + 8) * 64 + cc * 2));
                asm volatile("st.shared.b32 [%0], %1;" :: "r"(a0), "r"(*(uint32_t*)&h0) : "memory");
                asm volatile("st.shared.b32 [%0], %1;" :: "r"(a1), "r"(*(uint32_t*)&h1) : "memory");
            }
        CPWAIT1();
        __syncthreads();

#pragma unroll
        for (int kk = 0; kk < 8; kk++) {
            int b = kk >> 1, klo = kk & 1;
            uint32_t pf[4][4], vh2[4][2], vl2[4][2];
#pragma unroll
            for (int i = 0; i < 4; i++) {
                uint32_t row = (uint32_t)(wm * 64 + i * 16 + la);
                uint32_t pc = (uint32_t)(klo * 32 + (lane >> 4) * 16);
                LDSM4(pf[i], Pb + b * 8192u + SW64(row * 64 + pc));
            }
#pragma unroll
            for (int j = 0; j < 4; j++) {
                uint32_t vrow = (uint32_t)(wn * 32 + j * 8 + (la & 7));
                uint32_t vc = (uint32_t)(klo * 32 + (la >> 3) * 16);
                LDSM2(vh2[j], Bb + b * 16384u + SW128(vrow * 128 + vc));
                LDSM2(vl2[j], Bb + b * 16384u + SW128(vrow * 128 + 64 + vc));
            }
#pragma unroll
            for (int i = 0; i < 4; i++)
#pragma unroll
                for (int j = 0; j < 4; j++) {
                    MMA_F16(o[i][j], pf[i], vh2[j]);
                    MMA_F16(o[i][j], pf[i], vl2[j]);
                }
        }
        __syncthreads();
        if (s < qb) { load_v(s + 1); CPCOMMIT(); }
    }

#pragma unroll
    for (int i = 0; i < 4; i++) {
        float inv0 = 1.f / lrow[i][0], inv1 = 1.f / lrow[i][1];
        int r0 = qb * 128 + wm * 64 + i * 16 + (lane >> 2);
#pragma unroll
        for (int j = 0; j < 4; j++) {
            int col = h * 128 + wn * 32 + j * 8 + (lane & 3) * 2;
            float2 v0 = make_float2(o[i][j][0] * inv0, o[i][j][1] * inv0);
            float2 v1 = make_float2(o[i][j][2] * inv1, o[i][j][3] * inv1);
            *reinterpret_cast<float2*>(attn + (size_t)r0 * HID + col) = v0;
            *reinterpret_cast<float2*>(attn + (size_t)(r0 + 8) * HID + col) = v1;
        }
    }
}

// ======================= int8 exact-ternary GEMM (weights), 3-stage =======================
// C[m,n] = sx[m] * sum_g sc[n,g] * sum_{k in g} (128*ahi+alo)[m,k] * q[n,k]
// A smem: 128 rows x 64B [hi(32B)|lo(32B)] SW64;  B smem: 128 rows x 64B (q 32B used) SW64.
#define T8_STAGE     16384
#define GEMM_SMEM_T8 49152

__global__ void __launch_bounds__(256, 1)
gemm_tern_i8(const int8_t* __restrict__ Ahi, const int8_t* __restrict__ Alo,
             const float* __restrict__ Sx,
             const int8_t* __restrict__ Q, const float* __restrict__ Sc,
             float* __restrict__ C,
             int lda, int ldb, int ldc, int K,
             long long bStr, long long cStr, long long sStr)
{
    int m0 = blockIdx.y * 128, n0 = blockIdx.x * 128;
    size_t z = blockIdx.z;
    Q  += z * bStr; Sc += z * sStr;
    C  += z * cStr;
    int S = K >> 5, G = K >> 7;

    extern __shared__ char smem[];
    uint32_t sb = smem_u32(smem);
    int tid = threadIdx.x, lane = tid & 31, wid = tid >> 5;
    int wm = wid >> 2, wn = wid & 3, la = lane & 15;

    const int8_t* Ahm = Ahi + (size_t)m0 * lda;
    const int8_t* Alm = Alo + (size_t)m0 * lda;
    const int8_t* Qn  = Q   + (size_t)n0 * ldb;

    float acc[4][4][4];
#pragma unroll
    for (int i = 0; i < 4; i++)
#pragma unroll
        for (int j = 0; j < 4; j++)
#pragma unroll
            for (int r = 0; r < 4; r++) acc[i][j][r] = 0.f;

    auto prefetch = [&](int s) {
        int k0 = s * 32;
        uint32_t buf = sb + (uint32_t)(s % 3) * T8_STAGE;
#pragma unroll
        for (int j = 0; j < 2; j++) {            // A: 512 16B chunks
            int id = tid + j * 256;
            int row = id >> 2, ch = id & 3;      // ch: 0,1 hi; 2,3 lo
            const int8_t* src = (ch < 2 ? Ahm : Alm)
                + (size_t)row * lda + k0 + (ch & 1) * 16;
            CPASYNC16(buf + SW64((uint32_t)(row * 64 + ch * 16)), src);
        }
        {                                        // B: 256 16B chunks
            int row = tid >> 1, c = tid & 1;
            const int8_t* src = Qn + (size_t)row * ldb + k0 + c * 16;
            CPASYNC16(buf + 8192u + SW64((uint32_t)(row * 64 + c * 16)), src);
        }
    };

    int acchi[4][4][4], acclo[4][4][4];

    auto compute = [&](int s) {
        uint32_t bufA = sb + (uint32_t)(s % 3) * T8_STAGE;
        uint32_t bufB = bufA + 8192u;
        uint32_t ahi4[4][4], alo4[4][4], bq[4][2];
#pragma unroll
        for (int i = 0; i < 4; i++) {
            uint32_t row = (uint32_t)(wm * 64 + i * 16 + la);
            uint32_t coff = (uint32_t)((lane >> 4) * 16);
            LDSM4(ahi4[i], bufA + SW64(row * 64 + coff));
            LDSM4(alo4[i], bufA + SW64(row * 64 + 32 + coff));
        }
#pragma unroll
        for (int j = 0; j < 4; j++) {
            uint32_t row = (uint32_t)(wn * 32 + j * 8 + (la & 7));
            uint32_t col = (uint32_t)((la >> 3) * 16);
            LDSM2(bq[j], bufB + SW64(row * 64 + col));
        }
#pragma unroll
        for (int i = 0; i < 4; i++)
#pragma unroll
            for (int j = 0; j < 4; j++) {
                MMA_S8(acchi[i][j], ahi4[i], bq[j]);
                MMA_S8(acclo[i][j], alo4[i], bq[j]);
            }
    };

    prefetch(0); CPCOMMIT();
    prefetch(1); CPCOMMIT();
    for (int g = 0; g < G; g++) {
#pragma unroll
        for (int i = 0; i < 4; i++)
#pragma unroll
            for (int j = 0; j < 4; j++)
#pragma unroll
                for (int r = 0; r < 4; r++) { acchi[i][j][r] = 0; acclo[i][j][r] = 0; }

#pragma unroll
        for (int s4 = 0; s4 < 4; s4++) {
            int s = g * 4 + s4;
            CPWAIT1();
            __syncthreads();
            compute(s);
            if (s + 2 < S) { prefetch(s + 2); CPCOMMIT(); }
        }
#pragma unroll
        for (int j = 0; j < 4; j++) {
            int col = n0 + wn * 32 + j * 8 + (lane & 3) * 2;
            float s0 = __ldg(Sc + (size_t)col * G + g);
            float s1 = __ldg(Sc + (size_t)(col + 1) * G + g);
#pragma unroll
            for (int i = 0; i < 4; i++) {
                acc[i][j][0] = fmaf(s0, (float)((acchi[i][j][0] << 7) + acclo[i][j][0]), acc[i][j][0]);
                acc[i][j][1] = fmaf(s1, (float)((acchi[i][j][1] << 7) + acclo[i][j][1]), acc[i][j][1]);
                acc[i][j][2] = fmaf(s0, (float)((acchi[i][j][2] << 7) + acclo[i][j][2]), acc[i][j][2]);
                acc[i][j][3] = fmaf(s1, (float)((acchi[i][j][3] << 7) + acclo[i][j][3]), acc[i][j][3]);
            }
        }
    }

    int r0 = m0 + wm * 64, c0 = n0 + wn * 32;
#pragma unroll
    for (int i = 0; i < 4; i++) {
        int row = r0 + i * 16 + (lane >> 2);
        float sa0 = __ldg(Sx + row), sa1 = __ldg(Sx + row + 8);
#pragma unroll
        for (int j = 0; j < 4; j++) {
            int col = c0 + j * 8 + (lane & 3) * 2;
            float2 o0 = make_float2(acc[i][j][0] * sa0, acc[i][j][1] * sa0);
            float2 o1 = make_float2(acc[i][j][2] * sa1, acc[i][j][3] * sa1);
            *reinterpret_cast<float2*>(C + (size_t)row * ldc + col) = o0;
            *reinterpret_cast<float2*>(C + (size_t)(row + 8) * ldc + col) = o1;
        }
    }
}

// ======================= launch =======================
extern "C" void kernel_launch(void* const* d_in, const int* in_sizes, int n_in,
                              void* d_out, int out_size) {
    const float* x    = (const float*)d_in[0];
    const int*   mask = (const int*)d_in[1];
    const float* w_in[4] = {(const float*)d_in[2], (const float*)d_in[3],
                            (const float*)d_in[4], (const float*)d_in[5]};
    float* out = (float*)d_out;

    int8_t *p_wq8, *p_xhi, *p_xlo, *p_ahi, *p_alo;
    float *p_wsc, *p_sx, *p_sa, *p_proj, *p_attn;
    cudaGetSymbolAddress((void**)&p_wq8,  g_wq8);
    cudaGetSymbolAddress((void**)&p_wsc,  g_wsc);
    cudaGetSymbolAddress((void**)&p_xhi,  g_xhi);
    cudaGetSymbolAddress((void**)&p_xlo,  g_xlo);
    cudaGetSymbolAddress((void**)&p_sx,   g_sx);
    cudaGetSymbolAddress((void**)&p_ahi,  g_ahi);
    cudaGetSymbolAddress((void**)&p_alo,  g_alo);
    cudaGetSymbolAddress((void**)&p_sa,   g_sa);
    cudaGetSymbolAddress((void**)&p_proj, g_proj);
    cudaGetSymbolAddress((void**)&p_attn, g_attn);

    cudaFuncSetAttribute(gemm_tern_i8,
        cudaFuncAttributeMaxDynamicSharedMemorySize, GEMM_SMEM_T8);
    cudaFuncSetAttribute(flash_kernel,
        cudaFuncAttributeMaxDynamicSharedMemorySize, FL_SMEM);

    rope_tables_kernel<<<SQ, HALF>>>();

    for (int m = 0; m < 4; m++)
        quantize_tern_kernel<<<(HID * HID / GS) / 8, 256>>>(
            w_in[m], p_wq8 + (size_t)m * HID * HID, p_wsc + (size_t)m * HID * 16);

    quant8_kernel<<<SQ, 256>>>(x, p_xhi, p_xlo, p_sx);

    // q,k,v projections batched over z (int8 exact-ternary path)
    gemm_tern_i8<<<dim3(16, 16, 3), 256, GEMM_SMEM_T8>>>(
        p_xhi, p_xlo, p_sx, p_wq8, p_wsc, p_proj,
        HID, HID, HID, HID,
        (long long)HID * HID, (long long)SQ * HID, (long long)HID * 16);

    rope_reshape_kernel<<<dim3(SQ, NH), HALF>>>(0);
    rope_reshape_kernel<<<dim3(SQ, NH), HALF>>>(1);
    vt_split_kernel<<<dim3(SQ / 32, HD / 32, NH), dim3(32, 8)>>>();

    // fused attention
    flash_kernel<<<dim3(NH, 16), 256, FL_SMEM>>>(mask, p_attn);

    quant8_kernel<<<SQ, 256>>>(p_attn, p_ahi, p_alo, p_sa);

    // output projection (int8 exact-ternary path)
    gemm_tern_i8<<<dim3(16, 16, 1), 256, GEMM_SMEM_T8>>>(
        p_ahi, p_alo, p_sa, p_wq8 + 3 * (size_t)HID * HID, p_wsc + 3 * (size_t)HID * 16, out,
        HID, HID, HID, HID, 0LL, 0LL, 0LL);
}

// round 17
// speedup vs baseline: 2.0568x; 2.0568x over previous
#include <cuda_runtime.h>
#include <cuda_bf16.h>
#include <cuda_fp16.h>
#include <math.h>
#include <stdint.h>

#define SQ   2048
#define HID  2048
#define NH   16
#define HD   128
#define HALF 64
#define GS   128
#define NEG_INF (-3.402823e38f)

// ======================= PTX helpers (baseline sm_103 — NO tcgen05) =======================
__device__ __forceinline__ uint32_t smem_u32(const void* p) {
    uint32_t a;
    asm("{ .reg .u64 t; cvta.to.shared.u64 t, %1; cvt.u32.u64 %0, t; }" : "=r"(a) : "l"(p));
    return a;
}
#define SW128(o) ((o) ^ (((o) >> 3) & 0x70))
#define SW64(o)  ((o) ^ (((o) >> 3) & 0x30))

#define CPASYNC16(dst, src) \
    asm volatile("cp.async.cg.shared.global [%0], [%1], 16;" :: "r"(dst), "l"(src))
#define CPCOMMIT() asm volatile("cp.async.commit_group;" ::: "memory")
#define CPWAIT1()  asm volatile("cp.async.wait_group 1;" ::: "memory")

#define LDSM4(r, addr) \
    asm volatile("ldmatrix.sync.aligned.m8n8.x4.shared.b16 {%0,%1,%2,%3}, [%4];" \
                 : "=r"((r)[0]), "=r"((r)[1]), "=r"((r)[2]), "=r"((r)[3]) : "r"(addr))
#define LDSM2(r, addr) \
    asm volatile("ldmatrix.sync.aligned.m8n8.x2.shared.b16 {%0,%1}, [%2];" \
                 : "=r"((r)[0]), "=r"((r)[1]) : "r"(addr))

#define MMA_BF16(d, a, b) \
    asm volatile("mma.sync.aligned.m16n8k16.row.col.f32.bf16.bf16.f32 " \
                 "{%0,%1,%2,%3}, {%4,%5,%6,%7}, {%8,%9}, {%0,%1,%2,%3};" \
                 : "+f"((d)[0]), "+f"((d)[1]), "+f"((d)[2]), "+f"((d)[3]) \
                 : "r"((a)[0]), "r"((a)[1]), "r"((a)[2]), "r"((a)[3]), \
                   "r"((b)[0]), "r"((b)[1]))
#define MMA_F16(d, a, b) \
    asm volatile("mma.sync.aligned.m16n8k16.row.col.f32.f16.f16.f32 " \
                 "{%0,%1,%2,%3}, {%4,%5,%6,%7}, {%8,%9}, {%0,%1,%2,%3};" \
                 : "+f"((d)[0]), "+f"((d)[1]), "+f"((d)[2]), "+f"((d)[3]) \
                 : "r"((a)[0]), "r"((a)[1]), "r"((a)[2]), "r"((a)[3]), \
                   "r"((b)[0]), "r"((b)[1]))

// ======================= device scratch =======================
__device__ __nv_bfloat16 g_wq[4][(size_t)HID * HID];   // ternary q in bf16 (exact)
__device__ float         g_wsc[4][(size_t)HID * 16];   // per-row per-K-group scales
__device__ __nv_bfloat16 g_xh[(size_t)SQ * HID];
__device__ __nv_bfloat16 g_xl[(size_t)SQ * HID];
__device__ __nv_bfloat16 g_qh[NH][SQ * HD], g_ql[NH][SQ * HD];
__device__ __nv_bfloat16 g_kh[NH][SQ * HD], g_kl[NH][SQ * HD];
__device__ __half        g_vth[NH][HD * SQ], g_vtl[NH][HD * SQ];  // V^T [d][s] fp16 hi/lo
__device__ float         g_attn[(size_t)SQ * HID];
__device__ __nv_bfloat16 g_ah[(size_t)SQ * HID], g_al[(size_t)SQ * HID];
__device__ float         g_cos[SQ * HALF], g_sin[SQ * HALF];

__device__ __forceinline__ void bsplit(float x, __nv_bfloat16& h, __nv_bfloat16& l) {
    h = __float2bfloat16(x);
    l = __float2bfloat16(x - __bfloat162float(h));
}

// ======================= small kernels =======================
__global__ void rope_tables_kernel() {
    int s = blockIdx.x, i = threadIdx.x;
    float inv = (float)(1.0 / pow(10000.0, (double)i / 64.0));
    float ph = (float)s * inv;
    g_cos[s * HALF + i] = cosf(ph);
    g_sin[s * HALF + i] = sinf(ph);
}

// one warp per 128-elem group; all 4 weight matrices in one launch (blockIdx.y)
__global__ void quantize_tern_kernel(const float* __restrict__ w0, const float* __restrict__ w1,
                                     const float* __restrict__ w2, const float* __restrict__ w3) {
    int m = blockIdx.y;
    const float* w = (m == 0) ? w0 : (m == 1) ? w1 : (m == 2) ? w2 : w3;
    __nv_bfloat16* q = g_wq[m];
    float* sc = g_wsc[m];
    int gid  = blockIdx.x * 8 + (threadIdx.x >> 5);
    int lane = threadIdx.x & 31;
    size_t base = (size_t)gid * GS + lane * 4;
    float4 v = *reinterpret_cast<const float4*>(w + base);
    float s = fabsf(v.x) + fabsf(v.y) + fabsf(v.z) + fabsf(v.w);
#pragma unroll
    for (int off = 16; off; off >>= 1) s += __shfl_xor_sync(0xffffffffu, s, off);
    float scale = fmaxf(s * 0.0078125f, 1e-8f);
    float vv[4] = {v.x, v.y, v.z, v.w};
    __nv_bfloat16 qv[4];
#pragma unroll
    for (int j = 0; j < 4; j++) {
        float wn = vv[j] / scale;
        qv[j] = __float2bfloat16((wn > 0.5f) ? 1.0f : ((wn < -0.5f) ? -1.0f : 0.0f));
    }
    reinterpret_cast<__nv_bfloat162*>(q + base)[0] = {qv[0], qv[1]};
    reinterpret_cast<__nv_bfloat162*>(q + base)[1] = {qv[2], qv[3]};
    if (lane == 0) sc[gid] = scale;
}

__global__ void split_kernel(const float* __restrict__ x,
                             __nv_bfloat16* __restrict__ oh,
                             __nv_bfloat16* __restrict__ ol) {
    size_t i = ((size_t)blockIdx.x * 256 + threadIdx.x) * 4;
    float4 v = *reinterpret_cast<const float4*>(x + i);
    float vv[4] = {v.x, v.y, v.z, v.w};
    __nv_bfloat16 h[4], l[4];
#pragma unroll
    for (int j = 0; j < 4; j++) bsplit(vv[j], h[j], l[j]);
    reinterpret_cast<__nv_bfloat162*>(oh + i)[0] = {h[0], h[1]};
    reinterpret_cast<__nv_bfloat162*>(oh + i)[1] = {h[2], h[3]};
    reinterpret_cast<__nv_bfloat162*>(ol + i)[0] = {l[0], l[1]};
    reinterpret_cast<__nv_bfloat162*>(ol + i)[1] = {l[2], l[3]};
}

// ======================= 2-term exact-ternary GEMM (weights), 3-stage =======================
// C[m,n] = sum_g scale[n,g] * sum_{k in g} (Ah+Al)[m,k] * q[n,k]
// MODE 0: plain fp32 C output (out-projection).
// MODE 1: fused QKV epilogue — z=0/1: RoPE + bf16 hi/lo split into g_qh/g_ql / g_kh/g_kl;
//         z=2: transpose + fp16 hi/lo split into g_vth/g_vtl. n-tile == head.
#define T_STAGE      24576
#define GEMM_SMEM_T  73728
#define YT_LD        130   // EVEN stride: keeps float2 epilogue accesses 8B-aligned
                           // (129 caused misaligned-address trap; 2-way conflicts acceptable)

template<int MODE>
__global__ void __launch_bounds__(256, 1)
gemm_tern(const __nv_bfloat16* __restrict__ Ah, const __nv_bfloat16* __restrict__ Al,
          const __nv_bfloat16* __restrict__ Q, const float* __restrict__ Sc,
          float* __restrict__ C,
          int lda, int ldb, int ldc, int K,
          long long aStr, long long bStr, long long cStr, long long sStr)
{
    int m0 = blockIdx.y * 128, n0 = blockIdx.x * 128;
    int z = blockIdx.z;
    Ah += (size_t)z * aStr; Al += (size_t)z * aStr;
    Q  += (size_t)z * bStr; Sc += (size_t)z * sStr;
    C  += (size_t)z * cStr;
    int S = K >> 5, G = K >> 7;

    extern __shared__ char smem[];
    uint32_t sb = smem_u32(smem);
    int tid = threadIdx.x, lane = tid & 31, wid = tid >> 5;
    int wm = wid >> 2, wn = wid & 3, la = lane & 15;

    const __nv_bfloat16* Ahm = Ah + (size_t)m0 * lda;
    const __nv_bfloat16* Alm = Al + (size_t)m0 * lda;
    const __nv_bfloat16* Qn  = Q  + (size_t)n0 * ldb;

    float acc[4][4][4];
#pragma unroll
    for (int i = 0; i < 4; i++)
#pragma unroll
        for (int j = 0; j < 4; j++)
#pragma unroll
            for (int r = 0; r < 4; r++) acc[i][j][r] = 0.f;

    auto prefetch = [&](int s) {
        int k0 = s * 32;
        uint32_t buf = sb + (uint32_t)(s % 3) * T_STAGE;
#pragma unroll
        for (int j = 0; j < 4; j++) {
            int id = tid + j * 256;
            int row = id >> 3, ch = id & 7;
            const __nv_bfloat16* src =
                (ch < 4 ? Ahm : Alm) + (size_t)row * lda + k0 + (ch & 3) * 8;
            CPASYNC16(buf + SW128((uint32_t)(row * 128 + ch * 16)), src);
        }
#pragma unroll
        for (int j = 0; j < 2; j++) {
            int id = tid + j * 256;
            int row = id >> 2, c = id & 3;
            const __nv_bfloat16* src = Qn + (size_t)row * ldb + k0 + c * 8;
            CPASYNC16(buf + 16384u + SW64((uint32_t)(row * 64 + c * 16)), src);
        }
    };

    float accg[4][4][4];

    auto compute = [&](int s) {
        uint32_t bufA = sb + (uint32_t)(s % 3) * T_STAGE;
        uint32_t bufB = bufA + 16384u;
#pragma unroll
        for (int kk = 0; kk < 2; kk++) {
            uint32_t ah[4][4], al[4][4], bq[4][2];
#pragma unroll
            for (int i = 0; i < 4; i++) {
                uint32_t row = (uint32_t)(wm * 64 + i * 16 + la);
                uint32_t colh = (uint32_t)(kk * 32 + (lane >> 4) * 16);
                LDSM4(ah[i], bufA + SW128(row * 128 + colh));
                LDSM4(al[i], bufA + SW128(row * 128 + 64 + colh));
            }
#pragma unroll
            for (int j = 0; j < 4; j++) {
                uint32_t row = (uint32_t)(wn * 32 + j * 8 + (la & 7));
                uint32_t col = (uint32_t)(kk * 32 + (la >> 3) * 16);
                LDSM2(bq[j], bufB + SW64(row * 64 + col));
            }
#pragma unroll
            for (int i = 0; i < 4; i++)
#pragma unroll
                for (int j = 0; j < 4; j++) {
                    MMA_BF16(accg[i][j], ah[i], bq[j]);
                    MMA_BF16(accg[i][j], al[i], bq[j]);
                }
        }
    };

    prefetch(0); CPCOMMIT();
    prefetch(1); CPCOMMIT();
    for (int g = 0; g < G; g++) {
#pragma unroll
        for (int i = 0; i < 4; i++)
#pragma unroll
            for (int j = 0; j < 4; j++)
#pragma unroll
                for (int r = 0; r < 4; r++) accg[i][j][r] = 0.f;

#pragma unroll
        for (int s4 = 0; s4 < 4; s4++) {
            int s = g * 4 + s4;
            CPWAIT1();
            __syncthreads();
            compute(s);
            if (s + 2 < S) { prefetch(s + 2); CPCOMMIT(); }
        }
#pragma unroll
        for (int j = 0; j < 4; j++) {
            int col = n0 + wn * 32 + j * 8 + (lane & 3) * 2;
            float s0 = __ldg(Sc + (size_t)col * G + g);
            float s1 = __ldg(Sc + (size_t)(col + 1) * G + g);
#pragma unroll
            for (int i = 0; i < 4; i++) {
                acc[i][j][0] = fmaf(s0, accg[i][j][0], acc[i][j][0]);
                acc[i][j][1] = fmaf(s1, accg[i][j][1], acc[i][j][1]);
                acc[i][j][2] = fmaf(s0, accg[i][j][2], acc[i][j][2]);
                acc[i][j][3] = fmaf(s1, accg[i][j][3], acc[i][j][3]);
            }
        }
    }

    if (MODE == 0) {
        int r0 = m0 + wm * 64, c0 = n0 + wn * 32;
#pragma unroll
        for (int i = 0; i < 4; i++)
#pragma unroll
            for (int j = 0; j < 4; j++) {
                int row = r0 + i * 16 + (lane >> 2);
                int col = c0 + j * 8 + (lane & 3) * 2;
                float2 o0 = make_float2(acc[i][j][0], acc[i][j][1]);
                float2 o1 = make_float2(acc[i][j][2], acc[i][j][3]);
                *reinterpret_cast<float2*>(C + (size_t)row * ldc + col) = o0;
                *reinterpret_cast<float2*>(C + (size_t)(row + 8) * ldc + col) = o1;
            }
        return;
    }

    // ---- MODE 1: fused QKV epilogue via smem tile ----
    __syncthreads();                 // all warps done with stage buffers
    float* yt = reinterpret_cast<float*>(smem);
#pragma unroll
    for (int i = 0; i < 4; i++) {
        int row = wm * 64 + i * 16 + (lane >> 2);
#pragma unroll
        for (int j = 0; j < 4; j++) {
            int col = wn * 32 + j * 8 + (lane & 3) * 2;
            yt[row * YT_LD + col]           = acc[i][j][0];
            yt[row * YT_LD + col + 1]       = acc[i][j][1];
            yt[(row + 8) * YT_LD + col]     = acc[i][j][2];
            yt[(row + 8) * YT_LD + col + 1] = acc[i][j][3];
        }
    }
    __syncthreads();

    int h = blockIdx.x;              // n-tile == head
    if (z != 2) {
        // RoPE + bf16 hi/lo split: out[d] = x1*c - x2*s, out[d+64] = x1*s + x2*c
        __nv_bfloat16* dh = (z == 0 ? g_qh[h] : g_kh[h]);
        __nv_bfloat16* dl = (z == 0 ? g_ql[h] : g_kl[h]);
        int row = tid >> 1;
        int dbase = (tid & 1) * 32;
        int s = m0 + row;
        const float* yr = yt + row * YT_LD;
#pragma unroll
        for (int k = 0; k < 32; k += 2) {
            int d = dbase + k;
            float2 x1 = *reinterpret_cast<const float2*>(yr + d);
            float2 x2 = *reinterpret_cast<const float2*>(yr + d + 64);
            float2 cc = *reinterpret_cast<const float2*>(g_cos + s * HALF + d);
            float2 ss = *reinterpret_cast<const float2*>(g_sin + s * HALF + d);
            float o1a = x1.x * cc.x - x2.x * ss.x, o1b = x1.y * cc.y - x2.y * ss.y;
            float o2a = x1.x * ss.x + x2.x * cc.x, o2b = x1.y * ss.y + x2.y * cc.y;
            __nv_bfloat16 h1a, l1a, h1b, l1b, h2a, l2a, h2b, l2b;
            bsplit(o1a, h1a, l1a); bsplit(o1b, h1b, l1b);
            bsplit(o2a, h2a, l2a); bsplit(o2b, h2b, l2b);
            *reinterpret_cast<__nv_bfloat162*>(dh + (size_t)s * HD + d)      = {h1a, h1b};
            *reinterpret_cast<__nv_bfloat162*>(dh + (size_t)s * HD + d + 64) = {h2a, h2b};
            *reinterpret_cast<__nv_bfloat162*>(dl + (size_t)s * HD + d)      = {l1a, l1b};
            *reinterpret_cast<__nv_bfloat162*>(dl + (size_t)s * HD + d + 64) = {l2a, l2b};
        }
    } else {
        // V transpose + fp16 hi/lo split -> g_vt[h][d][s]
        int d = tid >> 1;
        int rbase = (tid & 1) * 64;
        __half* vh = g_vth[h] + (size_t)d * SQ + m0 + rbase;
        __half* vl = g_vtl[h] + (size_t)d * SQ + m0 + rbase;
#pragma unroll
        for (int k = 0; k < 64; k += 2) {
            float v0 = yt[(rbase + k) * YT_LD + d];
            float v1 = yt[(rbase + k + 1) * YT_LD + d];
            __half h0 = __float2half(v0), h1 = __float2half(v1);
            __half l0 = __float2half(v0 - __half2float(h0));
            __half l1 = __float2half(v1 - __half2float(h1));
            *reinterpret_cast<__half2*>(vh + k) = {h0, h1};
            *reinterpret_cast<__half2*>(vl + k) = {l0, l1};
        }
    }
}

// ======================= flash attention (proven R9 version) =======================
#define FL_SMEM 231424
#define FL_SCALE 0.08838834764831845f

__global__ void __launch_bounds__(256, 1)
flash_kernel(const int* __restrict__ mask, float* __restrict__ attn) {
    int h  = blockIdx.x;
    int qb = 15 - (int)blockIdx.y;
    extern __shared__ char smem[];
    uint32_t sb = smem_u32(smem);
    const uint32_t Qb = sb, Ab = sb + 65536u, Bb = sb + 131072u, Pb = sb + 196608u;
    float* red = reinterpret_cast<float*>(smem + 229376);
    int tid = threadIdx.x, lane = tid & 31, wid = tid >> 5;
    int wm = wid >> 2, wn = wid & 3, la = lane & 15;

    const __nv_bfloat16* qhp = g_qh[h]; const __nv_bfloat16* qlp = g_ql[h];
    const __nv_bfloat16* khp = g_kh[h]; const __nv_bfloat16* klp = g_kl[h];
    const __half* vhp = g_vth[h]; const __half* vlp = g_vtl[h];

#pragma unroll
    for (int j = 0; j < 16; j++) {
        int c = tid + j * 256; int b = c >> 10, id = c & 1023, row = id >> 3, ch = id & 7;
        const __nv_bfloat16* src = (ch < 4 ? qhp : qlp)
            + (size_t)(qb * 128 + row) * HD + b * 32 + (ch & 3) * 8;
        CPASYNC16(Qb + b * 16384u + SW128((uint32_t)(row * 128 + ch * 16)), src);
    }
    CPCOMMIT();

    auto load_k = [&](int kb) {
#pragma unroll
        for (int j = 0; j < 16; j++) {
            int c = tid + j * 256; int b = c >> 10, id = c & 1023, row = id >> 3, ch = id & 7;
            const __nv_bfloat16* src = (ch < 4 ? khp : klp)
                + (size_t)(kb * 128 + row) * HD + b * 32 + (ch & 3) * 8;
            CPASYNC16(Ab + b * 16384u + SW128((uint32_t)(row * 128 + ch * 16)), src);
        }
    };
    auto load_v = [&](int kb) {
#pragma unroll
        for (int j = 0; j < 16; j++) {
            int c = tid + j * 256; int b = c >> 10, id = c & 1023, row = id >> 3, ch = id & 7;
            const __half* src = (ch < 4 ? vhp : vlp)
                + (size_t)row * SQ + kb * 128 + b * 32 + (ch & 3) * 8;
            CPASYNC16(Bb + b * 16384u + SW128((uint32_t)(row * 128 + ch * 16)), src);
        }
    };
    load_k(0); CPCOMMIT();
    load_v(0); CPCOMMIT();

    float o[4][4][4];
    float mrow[4][2], lrow[4][2];
#pragma unroll
    for (int i = 0; i < 4; i++) {
#pragma unroll
        for (int j = 0; j < 4; j++)
#pragma unroll
            for (int r = 0; r < 4; r++) o[i][j][r] = 0.f;
        mrow[i][0] = NEG_INF; mrow[i][1] = NEG_INF;
        lrow[i][0] = 0.f;     lrow[i][1] = 0.f;
    }

    for (int s = 0; s <= qb; s++) {
        CPWAIT1();
        __syncthreads();

        float sacc[4][4][4];
#pragma unroll
        for (int i = 0; i < 4; i++)
#pragma unroll
            for (int j = 0; j < 4; j++)
#pragma unroll
                for (int r = 0; r < 4; r++) sacc[i][j][r] = 0.f;
#pragma unroll
        for (int kk = 0; kk < 8; kk++) {
            int b = kk >> 1, klo = kk & 1;
            uint32_t qh4[4][4], ql4[4][4], kh2[4][2], kl2[4][2];
#pragma unroll
            for (int i = 0; i < 4; i++) {
                uint32_t row = (uint32_t)(wm * 64 + i * 16 + la);
                uint32_t colh = (uint32_t)(klo * 32 + (lane >> 4) * 16);
                LDSM4(qh4[i], Qb + b * 16384u + SW128(row * 128 + colh));
                LDSM4(ql4[i], Qb + b * 16384u + SW128(row * 128 + 64 + colh));
            }
#pragma unroll
            for (int j = 0; j < 4; j++) {
                uint32_t krow = (uint32_t)(wn * 32 + j * 8 + (la & 7));
                uint32_t kc = (uint32_t)(klo * 32 + (la >> 3) * 16);
                LDSM2(kh2[j], Ab + b * 16384u + SW128(krow * 128 + kc));
                LDSM2(kl2[j], Ab + b * 16384u + SW128(krow * 128 + 64 + kc));
            }
#pragma unroll
            for (int i = 0; i < 4; i++)
#pragma unroll
                for (int j = 0; j < 4; j++) {
                    MMA_BF16(sacc[i][j], qh4[i], kh2[j]);
                    MMA_BF16(sacc[i][j], qh4[i], kl2[j]);
                    MMA_BF16(sacc[i][j], ql4[i], kh2[j]);
                }
        }

        bool diag = (s == qb);
#pragma unroll
        for (int j = 0; j < 4; j++) {
            int c0 = wn * 32 + j * 8 + (lane & 3) * 2;
            int cg = s * 128 + c0;
            bool mk0 = (__ldg(mask + cg) != 0), mk1 = (__ldg(mask + cg + 1) != 0);
#pragma unroll
            for (int i = 0; i < 4; i++) {
                int rg0 = qb * 128 + wm * 64 + i * 16 + (lane >> 2);
                int rg1 = rg0 + 8;
                float v0 = sacc[i][j][0] * FL_SCALE;
                float v1 = sacc[i][j][1] * FL_SCALE;
                float v2 = sacc[i][j][2] * FL_SCALE;
                float v3 = sacc[i][j][3] * FL_SCALE;
                if (!mk0 || (diag && cg     > rg0)) v0 = NEG_INF;
                if (!mk1 || (diag && cg + 1 > rg0)) v1 = NEG_INF;
                if (!mk0 || (diag && cg     > rg1)) v2 = NEG_INF;
                if (!mk1 || (diag && cg + 1 > rg1)) v3 = NEG_INF;
                sacc[i][j][0] = v0; sacc[i][j][1] = v1;
                sacc[i][j][2] = v2; sacc[i][j][3] = v3;
            }
        }

#pragma unroll
        for (int i = 0; i < 4; i++) {
            float a0 = NEG_INF, a1 = NEG_INF;
#pragma unroll
            for (int j = 0; j < 4; j++) {
                a0 = fmaxf(a0, fmaxf(sacc[i][j][0], sacc[i][j][1]));
                a1 = fmaxf(a1, fmaxf(sacc[i][j][2], sacc[i][j][3]));
            }
            a0 = fmaxf(a0, __shfl_xor_sync(0xffffffffu, a0, 1));
            a0 = fmaxf(a0, __shfl_xor_sync(0xffffffffu, a0, 2));
            a1 = fmaxf(a1, __shfl_xor_sync(0xffffffffu, a1, 1));
            a1 = fmaxf(a1, __shfl_xor_sync(0xffffffffu, a1, 2));
            if ((lane & 3) == 0) {
                int r0 = wm * 64 + i * 16 + (lane >> 2);
                red[r0 * 4 + wn] = a0;
                red[(r0 + 8) * 4 + wn] = a1;
            }
        }
        __syncthreads();

        float fsc[4][2], mnew[4][2];
#pragma unroll
        for (int i = 0; i < 4; i++)
#pragma unroll
            for (int rs = 0; rs < 2; rs++) {
                int r0 = wm * 64 + i * 16 + (lane >> 2) + rs * 8;
                float4 rv = *reinterpret_cast<float4*>(red + r0 * 4);
                float rm = fmaxf(fmaxf(rv.x, rv.y), fmaxf(rv.z, rv.w));
                float mn = fmaxf(mrow[i][rs], rm);
                fsc[i][rs] = __expf(mrow[i][rs] - mn);
                mnew[i][rs] = mn;
                mrow[i][rs] = mn;
            }

        float ps[4][2];
#pragma unroll
        for (int i = 0; i < 4; i++) { ps[i][0] = 0.f; ps[i][1] = 0.f; }
#pragma unroll
        for (int i = 0; i < 4; i++)
#pragma unroll
            for (int j = 0; j < 4; j++) {
                float p0 = __expf(sacc[i][j][0] - mnew[i][0]);
                float p1 = __expf(sacc[i][j][1] - mnew[i][0]);
                float p2 = __expf(sacc[i][j][2] - mnew[i][1]);
                float p3 = __expf(sacc[i][j][3] - mnew[i][1]);
                sacc[i][j][0] = p0; sacc[i][j][1] = p1;
                sacc[i][j][2] = p2; sacc[i][j][3] = p3;
                ps[i][0] += p0 + p1; ps[i][1] += p2 + p3;
            }
        __syncthreads();
#pragma unroll
        for (int i = 0; i < 4; i++) {
            float a0 = ps[i][0], a1 = ps[i][1];
            a0 += __shfl_xor_sync(0xffffffffu, a0, 1);
            a0 += __shfl_xor_sync(0xffffffffu, a0, 2);
            a1 += __shfl_xor_sync(0xffffffffu, a1, 1);
            a1 += __shfl_xor_sync(0xffffffffu, a1, 2);
            if ((lane & 3) == 0) {
                int r0 = wm * 64 + i * 16 + (lane >> 2);
                red[r0 * 4 + wn] = a0;
                red[(r0 + 8) * 4 + wn] = a1;
            }
        }
        __syncthreads();
#pragma unroll
        for (int i = 0; i < 4; i++)
#pragma unroll
            for (int rs = 0; rs < 2; rs++) {
                int r0 = wm * 64 + i * 16 + (lane >> 2) + rs * 8;
                float4 rv = *reinterpret_cast<float4*>(red + r0 * 4);
                float rsum = rv.x + rv.y + rv.z + rv.w;
                lrow[i][rs] = lrow[i][rs] * fsc[i][rs] + rsum;
            }
#pragma unroll
        for (int i = 0; i < 4; i++)
#pragma unroll
            for (int j = 0; j < 4; j++) {
                o[i][j][0] *= fsc[i][0]; o[i][j][1] *= fsc[i][0];
                o[i][j][2] *= fsc[i][1]; o[i][j][3] *= fsc[i][1];
            }

        if (s < qb) { load_k(s + 1); CPCOMMIT(); }

#pragma unroll
        for (int i = 0; i < 4; i++)
#pragma unroll
            for (int j = 0; j < 4; j++) {
                int c0 = wn * 32 + j * 8 + (lane & 3) * 2;
                int b = c0 >> 5, cc = c0 & 31;
                int r0 = wm * 64 + i * 16 + (lane >> 2);
                __half2 h0 = __floats2half2_rn(sacc[i][j][0], sacc[i][j][1]);
                __half2 h1 = __floats2half2_rn(sacc[i][j][2], sacc[i][j][3]);
                uint32_t a0 = Pb + b * 8192u + SW64((uint32_t)(r0 * 64 + cc * 2));
                uint32_t a1 = Pb + b * 8192u + SW64((uint32_t)((r0 + 8) * 64 + cc * 2));
                asm volatile("st.shared.b32 [%0], %1;" :: "r"(a0), "r"(*(uint32_t*)&h0) : "memory");
                asm volatile("st.shared.b32 [%0], %1;" :: "r"(a1), "r"(*(uint32_t*)&h1) : "memory");
            }
        CPWAIT1();
        __syncthreads();

#pragma unroll
        for (int kk = 0; kk < 8; kk++) {
            int b = kk >> 1, klo = kk & 1;
            uint32_t pf[4][4], vh2[4][2], vl2[4][2];
#pragma unroll
            for (int i = 0; i < 4; i++) {
                uint32_t row = (uint32_t)(wm * 64 + i * 16 + la);
                uint32_t pc = (uint32_t)(klo * 32 + (lane >> 4) * 16);
                LDSM4(pf[i], Pb + b * 8192u + SW64(row * 64 + pc));
            }
#pragma unroll
            for (int j = 0; j < 4; j++) {
                uint32_t vrow = (uint32_t)(wn * 32 + j * 8 + (la & 7));
                uint32_t vc = (uint32_t)(klo * 32 + (la >> 3) * 16);
                LDSM2(vh2[j], Bb + b * 16384u + SW128(vrow * 128 + vc));
                LDSM2(vl2[j], Bb + b * 16384u + SW128(vrow * 128 + 64 + vc));
            }
#pragma unroll
            for (int i = 0; i < 4; i++)
#pragma unroll
                for (int j = 0; j < 4; j++) {
                    MMA_F16(o[i][j], pf[i], vh2[j]);
                    MMA_F16(o[i][j], pf[i], vl2[j]);
                }
        }
        __syncthreads();
        if (s < qb) { load_v(s + 1); CPCOMMIT(); }
    }

#pragma unroll
    for (int i = 0; i < 4; i++) {
        float inv0 = 1.f / lrow[i][0], inv1 = 1.f / lrow[i][1];
        int r0 = qb * 128 + wm * 64 + i * 16 + (lane >> 2);
#pragma unroll
        for (int j = 0; j < 4; j++) {
            int col = h * 128 + wn * 32 + j * 8 + (lane & 3) * 2;
            float2 v0 = make_float2(o[i][j][0] * inv0, o[i][j][1] * inv0);
            float2 v1 = make_float2(o[i][j][2] * inv1, o[i][j][3] * inv1);
            *reinterpret_cast<float2*>(attn + (size_t)r0 * HID + col) = v0;
            *reinterpret_cast<float2*>(attn + (size_t)(r0 + 8) * HID + col) = v1;
        }
    }
}

// ======================= launch =======================
extern "C" void kernel_launch(void* const* d_in, const int* in_sizes, int n_in,
                              void* d_out, int out_size) {
    const float* x    = (const float*)d_in[0];
    const int*   mask = (const int*)d_in[1];
    float* out = (float*)d_out;

    __nv_bfloat16 *p_wq, *p_xh, *p_xl, *p_ah, *p_al;
    float *p_wsc, *p_attn;
    cudaGetSymbolAddress((void**)&p_wq,   g_wq);
    cudaGetSymbolAddress((void**)&p_wsc,  g_wsc);
    cudaGetSymbolAddress((void**)&p_xh,   g_xh);
    cudaGetSymbolAddress((void**)&p_xl,   g_xl);
    cudaGetSymbolAddress((void**)&p_attn, g_attn);
    cudaGetSymbolAddress((void**)&p_ah,   g_ah);
    cudaGetSymbolAddress((void**)&p_al,   g_al);

    cudaFuncSetAttribute(gemm_tern<0>,
        cudaFuncAttributeMaxDynamicSharedMemorySize, GEMM_SMEM_T);
    cudaFuncSetAttribute(gemm_tern<1>,
        cudaFuncAttributeMaxDynamicSharedMemorySize, GEMM_SMEM_T);
    cudaFuncSetAttribute(flash_kernel,
        cudaFuncAttributeMaxDynamicSharedMemorySize, FL_SMEM);

    rope_tables_kernel<<<SQ, HALF>>>();

    quantize_tern_kernel<<<dim3((HID * HID / GS) / 8, 4), 256>>>(
        (const float*)d_in[2], (const float*)d_in[3],
        (const float*)d_in[4], (const float*)d_in[5]);

    split_kernel<<<(SQ * HID) / 1024, 256>>>(x, p_xh, p_xl);

    // q,k,v projections with fused RoPE/transpose/split epilogue
    gemm_tern<1><<<dim3(16, 16, 3), 256, GEMM_SMEM_T>>>(
        p_xh, p_xl, p_wq, p_wsc, nullptr,
        HID, HID, HID, HID,
        0LL, (long long)HID * HID, 0LL, (long long)HID * 16);

    // fused attention: QK^T + causal softmax + PV
    flash_kernel<<<dim3(NH, 16), 256, FL_SMEM>>>(mask, p_attn);

    split_kernel<<<(SQ * HID) / 1024, 256>>>(p_attn, p_ah, p_al);

    // output projection
    gemm_tern<0><<<dim3(16, 16, 1), 256, GEMM_SMEM_T>>>(
        p_ah, p_al, p_wq + 3 * (size_t)HID * HID, p_wsc + 3 * (size_t)HID * 16, out,
        HID, HID, HID, HID, 0LL, 0LL, 0LL, 0LL);
}